// round 6
// baseline (speedup 1.0000x reference)
#include <cuda_runtime.h>

// Problem constants
#define AP 48        // paths
#define LL 64        // length
#define DD 64        // channels
#define MM 63        // L-1 (increments)
#define PER_GRAM (AP*AP)          // 2304

#define NPB 96                    // 48 X path-blocks + 48 Y path-blocks (64 rows each)
#define NTILE 48                  // (96*64)/128 tiles per dim
#define NTRI (NTILE*(NTILE+1)/2)  // 1176 upper-triangle tiles
#define NSLOT (NPB*(NPB+1)/2)     // 4656 active (pa<=pb) pair slots
#define BLK_ELEMS (64*64)         // one compact inc block

#define PDE_CTAS (NSLOT / 8)      // 582 CTAs x 8 warps

// Static scratch (no allocation allowed)
__device__ float g_inc[(size_t)NSLOT * BLK_ELEMS];   // 76 MB -> L2-resident
__device__ float g_Ks[NSLOT];
__device__ unsigned g_ctr;        // last-CTA counter; reset by last CTA each run

// slot index for pa <= pb over NPB blocks
__device__ __forceinline__ int slot_of(int pa, int pb) {
    return pa * NPB - (pa * (pa - 1)) / 2 + (pb - pa);
}

// smem layout (gemm):
//   sAdup [64 k][128 m] float2 {a,a}, stride ASTR (float2 units)
//   sB    [64 k][128 n] float,        stride BSTR
#define ASTR 129
#define BSTR 130
#define SMEM_BYTES (64*ASTR*8 + 64*BSTR*4)   // 99328 B

// ---------------------------------------------------------------------------
// Kernel 1: SYRK on padded increments (computed inline from X/Y).
// 128x128x64 tile (upper triangle, u >= t), packed fma.rn.f32x2.
// Epilogue scatters the tile's 4 (3 on diagonal) 64x64 sub-blocks into
// compact per-pair slots of g_inc.
// ---------------------------------------------------------------------------
__global__ void __launch_bounds__(256, 2) gemm_kernel(
    const float* __restrict__ X, const float* __restrict__ Y)
{
    extern __shared__ float smem[];
    float2* sAdup = reinterpret_cast<float2*>(smem);        // [k][m] duplicated
    float*  sB    = smem + 64 * ASTR * 2;                   // [k][n]

    // decode triangular tile index -> (t, u), u >= t
    int q = blockIdx.x;
    int t = 0;
    while (q >= NTILE - t) { q -= NTILE - t; t++; }
    const int u = t + q;

    const int gr0 = t * 128;   // global row base (A side)
    const int gc0 = u * 128;   // global col base (B side)
    const int tid = threadIdx.x;

    // load tiles, computing increments inline (coalesced across k)
    for (int idx = tid; idx < 128 * 64; idx += 256) {
        const int m = idx >> 6;
        const int k = idx & 63;
        {   // A side
            const int row = gr0 + m;
            const int blk = row >> 6;
            const int i   = row & 63;
            float v = 0.0f;
            if (i < MM) {
                const float* src = (blk < AP) ? (X + blk * (LL * DD))
                                              : (Y + (blk - AP) * (LL * DD));
                v = src[(i + 1) * DD + k] - src[i * DD + k];
            }
            sAdup[k * ASTR + m] = make_float2(v, v);
        }
        {   // B side
            const int row = gc0 + m;
            const int blk = row >> 6;
            const int i   = row & 63;
            float v = 0.0f;
            if (i < MM) {
                const float* src = (blk < AP) ? (X + blk * (LL * DD))
                                              : (Y + (blk - AP) * (LL * DD));
                v = src[(i + 1) * DD + k] - src[i * DD + k];
            }
            sB[k * BSTR + m] = v;
        }
    }
    __syncthreads();

    const int ty = tid >> 4;     // 0..15
    const int tx = tid & 15;     // 0..15
    const int m0 = ty * 8;
    const int n0 = 2 * tx;

    unsigned long long acc[8][4];
#pragma unroll
    for (int i = 0; i < 8; i++)
#pragma unroll
        for (int j = 0; j < 4; j++) acc[i][j] = 0ull;

    const float2* sA_ = sAdup + m0;
    const float*  sB_ = sB + n0;

#pragma unroll 8
    for (int k = 0; k < 64; k++) {
        unsigned long long aa[8], bb[4];
#pragma unroll
        for (int i = 0; i < 8; i++)
            aa[i] = *reinterpret_cast<const unsigned long long*>(
                        &sA_[k * ASTR + i]);
#pragma unroll
        for (int j = 0; j < 4; j++)
            bb[j] = *reinterpret_cast<const unsigned long long*>(
                        &sB_[k * BSTR + 32 * j]);
#pragma unroll
        for (int i = 0; i < 8; i++)
#pragma unroll
            for (int j = 0; j < 4; j++)
                asm("fma.rn.f32x2 %0, %1, %2, %0;"
                    : "+l"(acc[i][j]) : "l"(aa[i]), "l"(bb[j]));
    }

    // epilogue: scatter into compact slots.
    // rows m0..m0+7 all lie in sub-block r = ty>>3; col pair (n0+32j):
    // j=0,1 -> c=0 (cols 0..63), j=2,3 -> c=1.
    const int r  = ty >> 3;           // 0 or 1
    const int pa = 2 * t + r;
    const int li0 = m0 & 63;          // local row base within 64-block

#pragma unroll
    for (int c = 0; c < 2; c++) {
        const int pb = 2 * u + c;
        if (pa > pb) continue;        // only (r=1,c=0) on diagonal tiles
        float* dst = g_inc + (size_t)slot_of(pa, pb) * BLK_ELEMS;
#pragma unroll
        for (int i = 0; i < 8; i++) {
            float* row = dst + (li0 + i) * 64 + n0;
#pragma unroll
            for (int j = 0; j < 2; j++)
                *reinterpret_cast<float2*>(row + 32 * j) =
                    *reinterpret_cast<float2*>(&acc[i][2 * c + j]);
        }
    }
}

// ---------------------------------------------------------------------------
// Kernel 2: Goursat PDE recursion, one warp per active slot, reading the
// compact (L2-resident) inc blocks. Fused last-CTA final reduction.
// Row update is a prefix sum: new[j+1] = 1 + sum_{k<=j} c[k],
//   c[j] = prev[j+1] + prev[j]*(inc[i,j]-1).
// ---------------------------------------------------------------------------
__global__ void __launch_bounds__(256) pde_kernel(
    const float* __restrict__ X, const float* __restrict__ Y,
    float* __restrict__ out)
{
    const int warp = (blockIdx.x << 3) | (threadIdx.x >> 5);
    const int lane = threadIdx.x & 31;

    {
        const int s = warp;                       // slot 0..NSLOT-1
        // decode slot -> (pa, pb): pa = smallest with F(pa+1) > s,
        // F(p) = p*NPB - p(p-1)/2
        int pa = (int)((2.0f * NPB + 1.0f
                        - sqrtf((2.0f * NPB + 1.0f) * (2.0f * NPB + 1.0f)
                                - 8.0f * (float)s)) * 0.5f);
        if (pa > NPB - 1) pa = NPB - 1;
        if (pa < 0) pa = 0;
        while (pa > 0 && slot_of(pa, pa) > s) pa--;
        while (pa < NPB - 1 && slot_of(pa + 1, pa + 1) <= s) pa++;
        const int pb = pa + (s - slot_of(pa, pa));

        float w;
        if (pa < AP && pb >= AP) w = -2.0f / (float)PER_GRAM;           // XY
        else                     w = ((pa == pb) ? 1.0f : 2.0f)
                                     / (float)PER_GRAM;                 // XX/YY

        const float* __restrict__ base =
            g_inc + (size_t)s * BLK_ELEMS + 2 * lane;
        const bool lastl = (lane == 31);

        float prev0 = 1.0f;   // K[i][2l]
        float prev1 = 1.0f;   // K[i][2l+1]

        float2 inc = __ldg(reinterpret_cast<const float2*>(base));

        for (int i = 0; i < MM; i++) {
            float2 nxt = make_float2(0.0f, 0.0f);
            if (i + 1 < MM)
                nxt = __ldg(reinterpret_cast<const float2*>(
                                base + (i + 1) * 64));

            const float prev2 = __shfl_down_sync(0xffffffffu, prev0, 1);

            const float c0 = fmaf(prev0, inc.x - 1.0f, prev1);
            const float c1 = lastl ? 0.0f : fmaf(prev1, inc.y - 1.0f, prev2);

            const float sm = c0 + c1;
            float tcum = sm;
#pragma unroll
            for (int off = 1; off < 32; off <<= 1) {
                const float uu = __shfl_up_sync(0xffffffffu, tcum, off);
                if (lane >= off) tcum += uu;
            }
            const float E = tcum - sm;        // exclusive scan of pair sums

            prev0 = 1.0f + E;                 // new K[i+1][2l]
            prev1 = prev0 + c0;               // new K[i+1][2l+1]
            inc = nxt;
        }

        if (lastl) g_Ks[s] = w * prev1;       // weighted K[63][63]
    }

    // ---- fused final reduction: last CTA sums g_Ks + start term -----------
    __threadfence();
    __syncthreads();
    __shared__ bool s_is_last;
    if (threadIdx.x == 0)
        s_is_last = (atomicAdd(&g_ctr, 1u) == (unsigned)(gridDim.x - 1));
    __syncthreads();
    if (!s_is_last) return;

    __shared__ float sdata[256];
    const int tid = threadIdx.x;
    float s = 0.0f;
    for (int p = tid; p < NSLOT; p += 256) s += __ldcg(&g_Ks[p]);

    float s2 = 0.0f;
    for (int idx = tid; idx < AP * DD; idx += 256) {
        const int aa = idx >> 6;
        const int d  = idx & 63;
        const float diff = X[aa * (LL * DD) + d] - Y[aa * (LL * DD) + d];
        s2 = fmaf(diff, diff, s2);
    }
    s += s2 * (1.0f / (float)(AP * DD));

    sdata[tid] = s;
    __syncthreads();
    for (int k = 128; k > 0; k >>= 1) {
        if (tid < k) sdata[tid] += sdata[tid + k];
        __syncthreads();
    }
    if (tid == 0) {
        out[0] = sdata[0];
        g_ctr = 0u;              // reset for next graph replay
    }
}

// ---------------------------------------------------------------------------
extern "C" void kernel_launch(void* const* d_in, const int* in_sizes, int n_in,
                              void* d_out, int out_size)
{
    const float* X = (const float*)d_in[0];
    const float* Y = (const float*)d_in[1];
    float* out = (float*)d_out;

    static bool attr_done = false;
    if (!attr_done) {
        cudaFuncSetAttribute(gemm_kernel,
                             cudaFuncAttributeMaxDynamicSharedMemorySize,
                             SMEM_BYTES);
        attr_done = true;
    }

    gemm_kernel<<<NTRI, 256, SMEM_BYTES>>>(X, Y);
    pde_kernel<<<PDE_CTAS, 256>>>(X, Y, out);
}

// round 7
// speedup vs baseline: 1.4416x; 1.4416x over previous
#include <cuda_runtime.h>

// Problem constants
#define AP 48        // paths
#define LL 64        // length
#define DD 64        // channels
#define MM 63        // L-1 (increments)
#define PER_GRAM (AP*AP)          // 2304

#define NPB 96                    // 48 X blocks + 48 Y blocks (64 padded rows each)
#define ROWS (NPB*64)             // 6144
#define NTILE 48                  // 6144/128 tiles per dim
#define NTRI (NTILE*(NTILE+1)/2)  // 1176 upper-triangle tiles
#define NSLOT (NPB*(NPB+1)/2)     // 4656 active (pa<=pb) pair slots
#define BLK_ELEMS (64*64)

#define PDE_WARPS (NSLOT/2)       // 2328 warps, 2 pairs each
#define PDE_CTAS (PDE_WARPS/8)    // 291 CTAs x 8 warps

// Static scratch (no allocation allowed)
__device__ float g_dZ[(size_t)ROWS * 64];            // 1.5 MB padded increments
__device__ float g_inc[(size_t)NSLOT * BLK_ELEMS];   // 76 MB compact blocks
__device__ float g_Ks[NSLOT];
__device__ unsigned g_ctr;        // last-CTA counter; self-reset each run

__device__ __forceinline__ int slot_of(int pa, int pb) {
    return pa * NPB - (pa * (pa - 1)) / 2 + (pb - pa);
}

// gemm smem (R3-proven layout): A^T [k][m] stride 129, B^T [k][n] stride 130
#define SA_STRIDE 129
#define SB_STRIDE 130
#define SMEM_FLOATS (64*SA_STRIDE + 64*SB_STRIDE)
#define SMEM_BYTES (SMEM_FLOATS * sizeof(float))     // 66304 B

// ---------------------------------------------------------------------------
// Kernel 0: padded increments dZ[blk*64+i][d]; row i=63 zeroed
// ---------------------------------------------------------------------------
__global__ void __launch_bounds__(256) dz_kernel(
    const float* __restrict__ X, const float* __restrict__ Y)
{
    const int blk = blockIdx.x;
    const float* src = (blk < AP) ? (X + blk * (LL * DD))
                                  : (Y + (blk - AP) * (LL * DD));
    float* dst = g_dZ + (size_t)blk * (64 * DD);
    for (int idx = threadIdx.x; idx < 64 * DD; idx += 256) {
        const int i = idx >> 6;
        const int d = idx & 63;
        float v = 0.0f;
        if (i < MM) v = src[(i + 1) * DD + d] - src[i * DD + d];
        dst[idx] = v;
    }
}

// ---------------------------------------------------------------------------
// Kernel 1: SYRK G = dZ dZ^T, 128x128x64 tiles (u >= t), packed fma.rn.f32x2.
// R3-style mainloop (scalar A + mov-pack). Epilogue scatters the 4 (3 on
// diagonal) 64x64 sub-blocks to compact slots.
// ---------------------------------------------------------------------------
__global__ void __launch_bounds__(256, 2) gemm_kernel()
{
    extern __shared__ float smem[];
    float* sA = smem;                       // [64][SA_STRIDE]
    float* sB = smem + 64 * SA_STRIDE;      // [64][SB_STRIDE]

    int q = blockIdx.x;
    int t = 0;
    while (q >= NTILE - t) { q -= NTILE - t; t++; }
    const int u = t + q;

    const int gr0 = t * 128;
    const int gc0 = u * 128;
    const int tid = threadIdx.x;

    for (int idx = tid; idx < 128 * 64; idx += 256) {
        const int m = idx >> 6;
        const int k = idx & 63;
        sA[k * SA_STRIDE + m] = g_dZ[(size_t)(gr0 + m) * 64 + k];
        sB[k * SB_STRIDE + m] = g_dZ[(size_t)(gc0 + m) * 64 + k];
    }
    __syncthreads();

    const int ty = tid >> 4;     // 0..15
    const int tx = tid & 15;     // 0..15
    const int m0 = ty * 8;
    const int n0 = 2 * tx;

    unsigned long long acc[8][4];
#pragma unroll
    for (int i = 0; i < 8; i++)
#pragma unroll
        for (int j = 0; j < 4; j++) acc[i][j] = 0ull;

    const float* sA_ = sA + m0;
    const float* sB_ = sB + n0;

#pragma unroll 8
    for (int k = 0; k < 64; k++) {
        unsigned long long aa[8], bb[4];
#pragma unroll
        for (int i = 0; i < 8; i++) {
            const float a = sA_[k * SA_STRIDE + i];
            asm("mov.b64 %0, {%1, %1};" : "=l"(aa[i]) : "f"(a));
        }
#pragma unroll
        for (int j = 0; j < 4; j++)
            bb[j] = *reinterpret_cast<const unsigned long long*>(
                        &sB_[k * SB_STRIDE + 32 * j]);
#pragma unroll
        for (int i = 0; i < 8; i++)
#pragma unroll
            for (int j = 0; j < 4; j++)
                asm("fma.rn.f32x2 %0, %1, %2, %0;"
                    : "+l"(acc[i][j]) : "l"(aa[i]), "l"(bb[j]));
    }

    // epilogue: rows m0..m0+7 lie in sub-block r = ty>>3; j<2 -> c=0, j>=2 -> c=1
    const int r   = ty >> 3;
    const int pa  = 2 * t + r;
    const int li0 = m0 & 63;

#pragma unroll
    for (int c = 0; c < 2; c++) {
        const int pb = 2 * u + c;
        if (pa > pb) continue;            // only (r=1,c=0) on diagonal tiles
        float* dst = g_inc + (size_t)slot_of(pa, pb) * BLK_ELEMS;
#pragma unroll
        for (int i = 0; i < 8; i++) {
            float* row = dst + (li0 + i) * 64 + n0;
#pragma unroll
            for (int j = 0; j < 2; j++)
                *reinterpret_cast<float2*>(row + 32 * j) =
                    *reinterpret_cast<float2*>(&acc[i][2 * c + j]);
        }
    }
}

// ---------------------------------------------------------------------------
// slot -> (pa, pb) decode
// ---------------------------------------------------------------------------
__device__ __forceinline__ void decode_slot(int s, int& pa, int& pb) {
    int p = (int)((2.0f * NPB + 1.0f
                   - sqrtf((2.0f * NPB + 1.0f) * (2.0f * NPB + 1.0f)
                           - 8.0f * (float)s)) * 0.5f);
    if (p > NPB - 1) p = NPB - 1;
    if (p < 0) p = 0;
    while (p > 0 && slot_of(p, p) > s) p--;
    while (p < NPB - 1 && slot_of(p + 1, p + 1) <= s) p++;
    pa = p;
    pb = p + (s - slot_of(p, p));
}

__device__ __forceinline__ float weight_of(int pa, int pb) {
    if (pa < AP && pb >= AP) return -2.0f / (float)PER_GRAM;          // XY
    return ((pa == pb) ? 1.0f : 2.0f) / (float)PER_GRAM;              // XX/YY
}

// ---------------------------------------------------------------------------
// Kernel 2: Goursat PDE, TWO pairs per warp (independent recursions interleave
// -> 2x ILP on scan chain) with a 2-deep row prefetch ring per pair (MLP 4).
// Fused last-CTA final reduction.
// ---------------------------------------------------------------------------
__global__ void __launch_bounds__(256) pde_kernel(
    const float* __restrict__ X, const float* __restrict__ Y,
    float* __restrict__ out)
{
    const int warp = (blockIdx.x << 3) | (threadIdx.x >> 5);
    const int lane = threadIdx.x & 31;
    const bool lastl = (lane == 31);

    {
        const int sa = 2 * warp;
        const int sb = 2 * warp + 1;

        int paA, pbA, paB, pbB;
        decode_slot(sa, paA, pbA);
        decode_slot(sb, paB, pbB);
        const float wA = weight_of(paA, pbA);
        const float wB = weight_of(paB, pbB);

        const float* __restrict__ baseA = g_inc + (size_t)sa * BLK_ELEMS + 2 * lane;
        const float* __restrict__ baseB = g_inc + (size_t)sb * BLK_ELEMS + 2 * lane;

        float a0 = 1.0f, a1 = 1.0f;     // pair A: K[i][2l], K[i][2l+1]
        float b0 = 1.0f, b1 = 1.0f;     // pair B

        float2 bufA[2], bufB[2];
        bufA[0] = __ldg(reinterpret_cast<const float2*>(baseA));
        bufB[0] = __ldg(reinterpret_cast<const float2*>(baseB));
        bufA[1] = __ldg(reinterpret_cast<const float2*>(baseA + 64));
        bufB[1] = __ldg(reinterpret_cast<const float2*>(baseB + 64));

#pragma unroll 2
        for (int i = 0; i < MM; i++) {
            const float2 incA = bufA[i & 1];
            const float2 incB = bufB[i & 1];
            if (i + 2 < MM) {
                bufA[i & 1] = __ldg(reinterpret_cast<const float2*>(
                                        baseA + (i + 2) * 64));
                bufB[i & 1] = __ldg(reinterpret_cast<const float2*>(
                                        baseB + (i + 2) * 64));
            }

            const float a2 = __shfl_down_sync(0xffffffffu, a0, 1);
            const float b2 = __shfl_down_sync(0xffffffffu, b0, 1);

            const float cA0 = fmaf(a0, incA.x - 1.0f, a1);
            const float cB0 = fmaf(b0, incB.x - 1.0f, b1);
            const float cA1 = lastl ? 0.0f : fmaf(a1, incA.y - 1.0f, a2);
            const float cB1 = lastl ? 0.0f : fmaf(b1, incB.y - 1.0f, b2);

            const float sAx = cA0 + cA1;
            const float sBx = cB0 + cB1;
            float tA = sAx, tB = sBx;
#pragma unroll
            for (int off = 1; off < 32; off <<= 1) {
                const float uA = __shfl_up_sync(0xffffffffu, tA, off);
                const float uB = __shfl_up_sync(0xffffffffu, tB, off);
                if (lane >= off) { tA += uA; tB += uB; }
            }
            const float EA = tA - sAx;      // exclusive scans
            const float EB = tB - sBx;

            a0 = 1.0f + EA;  a1 = a0 + cA0;
            b0 = 1.0f + EB;  b1 = b0 + cB0;
        }

        if (lastl) {
            g_Ks[sa] = wA * a1;
            g_Ks[sb] = wB * b1;
        }
    }

    // ---- fused final reduction: last CTA sums g_Ks + start term -----------
    __threadfence();
    __syncthreads();
    __shared__ bool s_is_last;
    if (threadIdx.x == 0)
        s_is_last = (atomicAdd(&g_ctr, 1u) == (unsigned)(gridDim.x - 1));
    __syncthreads();
    if (!s_is_last) return;

    __shared__ float sdata[256];
    const int tid = threadIdx.x;
    float s = 0.0f;
    for (int p = tid; p < NSLOT; p += 256) s += __ldcg(&g_Ks[p]);

    float s2 = 0.0f;
    for (int idx = tid; idx < AP * DD; idx += 256) {
        const int aa = idx >> 6;
        const int d  = idx & 63;
        const float diff = X[aa * (LL * DD) + d] - Y[aa * (LL * DD) + d];
        s2 = fmaf(diff, diff, s2);
    }
    s += s2 * (1.0f / (float)(AP * DD));

    sdata[tid] = s;
    __syncthreads();
    for (int k = 128; k > 0; k >>= 1) {
        if (tid < k) sdata[tid] += sdata[tid + k];
        __syncthreads();
    }
    if (tid == 0) {
        out[0] = sdata[0];
        g_ctr = 0u;              // reset for next graph replay
    }
}

// ---------------------------------------------------------------------------
extern "C" void kernel_launch(void* const* d_in, const int* in_sizes, int n_in,
                              void* d_out, int out_size)
{
    const float* X = (const float*)d_in[0];
    const float* Y = (const float*)d_in[1];
    float* out = (float*)d_out;

    static bool attr_done = false;
    if (!attr_done) {
        cudaFuncSetAttribute(gemm_kernel,
                             cudaFuncAttributeMaxDynamicSharedMemorySize,
                             SMEM_BYTES);
        attr_done = true;
    }

    dz_kernel<<<NPB, 256>>>(X, Y);
    gemm_kernel<<<NTRI, 256, SMEM_BYTES>>>();
    pde_kernel<<<PDE_CTAS, 256>>>(X, Y, out);
}

// round 8
// speedup vs baseline: 1.6250x; 1.1272x over previous
#include <cuda_runtime.h>

// Problem constants
#define AP 48        // paths
#define LL 64        // length
#define DD 64        // channels
#define MM 63        // L-1 (increments)
#define PER_GRAM (AP*AP)          // 2304

#define NPB 96                    // 48 X blocks + 48 Y blocks (64 padded rows each)
#define ROWS (NPB*64)             // 6144
#define NTILE 48                  // 6144/128 tiles per dim
#define NTRI (NTILE*(NTILE+1)/2)  // 1176 upper-triangle tiles
#define NSLOT (NPB*(NPB+1)/2)     // 4656 active (pa<=pb) pair slots
#define BLK_ELEMS (64*64)

#define PDE_WARPS (NSLOT/2)       // 2328 warps, 2 pairs each
#define PDE_CTAS (PDE_WARPS/8)    // 291 CTAs x 8 warps

// Static scratch (no allocation allowed)
__device__ float g_dZ[(size_t)ROWS * 64];            // 1.5 MB padded increments
__device__ float g_inc[(size_t)NSLOT * BLK_ELEMS];   // 76 MB compact blocks
__device__ float g_Ks[NSLOT];
__device__ unsigned g_ctr;        // last-CTA counter; self-reset each run

__device__ __forceinline__ int slot_of(int pa, int pb) {
    return pa * NPB - (pa * (pa - 1)) / 2 + (pb - pa);
}

// gemm smem (R3-proven layout): A^T [k][m] stride 129, B^T [k][n] stride 130
#define SA_STRIDE 129
#define SB_STRIDE 130
#define SMEM_FLOATS (64*SA_STRIDE + 64*SB_STRIDE)
#define SMEM_BYTES (SMEM_FLOATS * sizeof(float))     // 66304 B

// ---------------------------------------------------------------------------
// Kernel 0: padded increments dZ[blk*64+i][d]; row i=63 zeroed.
// One float4 per thread, single full-chip wave (384 CTAs x 256 threads).
// ---------------------------------------------------------------------------
__global__ void __launch_bounds__(256) dz_kernel(
    const float* __restrict__ X, const float* __restrict__ Y)
{
    const int idx = blockIdx.x * 256 + threadIdx.x;   // float4 index, < 98304
    const int row = idx >> 4;       // padded row 0..6143
    const int d4  = idx & 15;       // float4 within row
    const int blk = row >> 6;
    const int i   = row & 63;

    float4 v = make_float4(0.f, 0.f, 0.f, 0.f);
    if (i < MM) {
        const float* src = (blk < AP) ? (X + blk * (LL * DD))
                                      : (Y + (blk - AP) * (LL * DD));
        const float4 hi = *reinterpret_cast<const float4*>(src + (i + 1) * DD + 4 * d4);
        const float4 lo = *reinterpret_cast<const float4*>(src + i * DD + 4 * d4);
        v = make_float4(hi.x - lo.x, hi.y - lo.y, hi.z - lo.z, hi.w - lo.w);
    }
    *reinterpret_cast<float4*>(g_dZ + (size_t)row * 64 + 4 * d4) = v;
}

// ---------------------------------------------------------------------------
// Kernel 1: SYRK G = dZ dZ^T, 128x128x64 tiles (u >= t), packed fma.rn.f32x2.
// Epilogue scatters the 4 (3 on diagonal) 64x64 sub-blocks to compact slots.
// ---------------------------------------------------------------------------
__global__ void __launch_bounds__(256, 2) gemm_kernel()
{
    extern __shared__ float smem[];
    float* sA = smem;                       // [64][SA_STRIDE]
    float* sB = smem + 64 * SA_STRIDE;      // [64][SB_STRIDE]

    int q = blockIdx.x;
    int t = 0;
    while (q >= NTILE - t) { q -= NTILE - t; t++; }
    const int u = t + q;

    const int gr0 = t * 128;
    const int gc0 = u * 128;
    const int tid = threadIdx.x;

    for (int idx = tid; idx < 128 * 64; idx += 256) {
        const int m = idx >> 6;
        const int k = idx & 63;
        sA[k * SA_STRIDE + m] = g_dZ[(size_t)(gr0 + m) * 64 + k];
        sB[k * SB_STRIDE + m] = g_dZ[(size_t)(gc0 + m) * 64 + k];
    }
    __syncthreads();

    const int ty = tid >> 4;     // 0..15
    const int tx = tid & 15;     // 0..15
    const int m0 = ty * 8;
    const int n0 = 2 * tx;

    unsigned long long acc[8][4];
#pragma unroll
    for (int i = 0; i < 8; i++)
#pragma unroll
        for (int j = 0; j < 4; j++) acc[i][j] = 0ull;

    const float* sA_ = sA + m0;
    const float* sB_ = sB + n0;

#pragma unroll 8
    for (int k = 0; k < 64; k++) {
        unsigned long long aa[8], bb[4];
#pragma unroll
        for (int i = 0; i < 8; i++) {
            const float a = sA_[k * SA_STRIDE + i];
            asm("mov.b64 %0, {%1, %1};" : "=l"(aa[i]) : "f"(a));
        }
#pragma unroll
        for (int j = 0; j < 4; j++)
            bb[j] = *reinterpret_cast<const unsigned long long*>(
                        &sB_[k * SB_STRIDE + 32 * j]);
#pragma unroll
        for (int i = 0; i < 8; i++)
#pragma unroll
            for (int j = 0; j < 4; j++)
                asm("fma.rn.f32x2 %0, %1, %2, %0;"
                    : "+l"(acc[i][j]) : "l"(aa[i]), "l"(bb[j]));
    }

    // epilogue: rows m0..m0+7 lie in sub-block r = ty>>3; j<2 -> c=0, j>=2 -> c=1
    const int r   = ty >> 3;
    const int pa  = 2 * t + r;
    const int li0 = m0 & 63;

#pragma unroll
    for (int c = 0; c < 2; c++) {
        const int pb = 2 * u + c;
        if (pa > pb) continue;            // only (r=1,c=0) on diagonal tiles
        float* dst = g_inc + (size_t)slot_of(pa, pb) * BLK_ELEMS;
#pragma unroll
        for (int i = 0; i < 8; i++) {
            float* row = dst + (li0 + i) * 64 + n0;
#pragma unroll
            for (int j = 0; j < 2; j++)
                *reinterpret_cast<float2*>(row + 32 * j) =
                    *reinterpret_cast<float2*>(&acc[i][2 * c + j]);
        }
    }
}

// ---------------------------------------------------------------------------
// slot -> (pa, pb) decode
// ---------------------------------------------------------------------------
__device__ __forceinline__ void decode_slot(int s, int& pa, int& pb) {
    int p = (int)((2.0f * NPB + 1.0f
                   - sqrtf((2.0f * NPB + 1.0f) * (2.0f * NPB + 1.0f)
                           - 8.0f * (float)s)) * 0.5f);
    if (p > NPB - 1) p = NPB - 1;
    if (p < 0) p = 0;
    while (p > 0 && slot_of(p, p) > s) p--;
    while (p < NPB - 1 && slot_of(p + 1, p + 1) <= s) p++;
    pa = p;
    pb = p + (s - slot_of(p, p));
}

__device__ __forceinline__ float weight_of(int pa, int pb) {
    if (pa < AP && pb >= AP) return -2.0f / (float)PER_GRAM;          // XY
    return ((pa == pb) ? 1.0f : 2.0f) / (float)PER_GRAM;              // XX/YY
}

// ---------------------------------------------------------------------------
// Kernel 2: Goursat PDE, TWO pairs per warp, 4-deep row prefetch ring per
// pair (MLP 8/warp -> row-load latency fully covered). Fused last-CTA
// final reduction.
// ---------------------------------------------------------------------------
__global__ void __launch_bounds__(256) pde_kernel(
    const float* __restrict__ X, const float* __restrict__ Y,
    float* __restrict__ out)
{
    const int warp = (blockIdx.x << 3) | (threadIdx.x >> 5);
    const int lane = threadIdx.x & 31;
    const bool lastl = (lane == 31);

    {
        const int sa = 2 * warp;
        const int sb = 2 * warp + 1;

        int paA, pbA, paB, pbB;
        decode_slot(sa, paA, pbA);
        decode_slot(sb, paB, pbB);
        const float wA = weight_of(paA, pbA);
        const float wB = weight_of(paB, pbB);

        const float* __restrict__ baseA = g_inc + (size_t)sa * BLK_ELEMS + 2 * lane;
        const float* __restrict__ baseB = g_inc + (size_t)sb * BLK_ELEMS + 2 * lane;

        float a0 = 1.0f, a1 = 1.0f;     // pair A: K[i][2l], K[i][2l+1]
        float b0 = 1.0f, b1 = 1.0f;     // pair B

        float2 bufA[4], bufB[4];
#pragma unroll
        for (int k = 0; k < 4; k++) {
            bufA[k] = __ldg(reinterpret_cast<const float2*>(baseA + k * 64));
            bufB[k] = __ldg(reinterpret_cast<const float2*>(baseB + k * 64));
        }

#pragma unroll 4
        for (int i = 0; i < MM; i++) {
            const float2 incA = bufA[i & 3];
            const float2 incB = bufB[i & 3];
            if (i + 4 < MM) {
                bufA[i & 3] = __ldg(reinterpret_cast<const float2*>(
                                        baseA + (i + 4) * 64));
                bufB[i & 3] = __ldg(reinterpret_cast<const float2*>(
                                        baseB + (i + 4) * 64));
            }

            const float a2 = __shfl_down_sync(0xffffffffu, a0, 1);
            const float b2 = __shfl_down_sync(0xffffffffu, b0, 1);

            const float cA0 = fmaf(a0, incA.x - 1.0f, a1);
            const float cB0 = fmaf(b0, incB.x - 1.0f, b1);
            const float cA1 = lastl ? 0.0f : fmaf(a1, incA.y - 1.0f, a2);
            const float cB1 = lastl ? 0.0f : fmaf(b1, incB.y - 1.0f, b2);

            const float sAx = cA0 + cA1;
            const float sBx = cB0 + cB1;
            float tA = sAx, tB = sBx;
#pragma unroll
            for (int off = 1; off < 32; off <<= 1) {
                const float uA = __shfl_up_sync(0xffffffffu, tA, off);
                const float uB = __shfl_up_sync(0xffffffffu, tB, off);
                if (lane >= off) { tA += uA; tB += uB; }
            }
            const float EA = tA - sAx;      // exclusive scans
            const float EB = tB - sBx;

            a0 = 1.0f + EA;  a1 = a0 + cA0;
            b0 = 1.0f + EB;  b1 = b0 + cB0;
        }

        if (lastl) {
            g_Ks[sa] = wA * a1;
            g_Ks[sb] = wB * b1;
        }
    }

    // ---- fused final reduction: last CTA sums g_Ks + start term -----------
    __threadfence();
    __syncthreads();
    __shared__ bool s_is_last;
    if (threadIdx.x == 0)
        s_is_last = (atomicAdd(&g_ctr, 1u) == (unsigned)(gridDim.x - 1));
    __syncthreads();
    if (!s_is_last) return;

    __shared__ float sdata[256];
    const int tid = threadIdx.x;
    float s = 0.0f;
    for (int p = tid; p < NSLOT; p += 256) s += __ldcg(&g_Ks[p]);

    float s2 = 0.0f;
    for (int idx = tid; idx < AP * DD; idx += 256) {
        const int aa = idx >> 6;
        const int d  = idx & 63;
        const float diff = X[aa * (LL * DD) + d] - Y[aa * (LL * DD) + d];
        s2 = fmaf(diff, diff, s2);
    }
    s += s2 * (1.0f / (float)(AP * DD));

    sdata[tid] = s;
    __syncthreads();
    for (int k = 128; k > 0; k >>= 1) {
        if (tid < k) sdata[tid] += sdata[tid + k];
        __syncthreads();
    }
    if (tid == 0) {
        out[0] = sdata[0];
        g_ctr = 0u;              // reset for next graph replay
    }
}

// ---------------------------------------------------------------------------
extern "C" void kernel_launch(void* const* d_in, const int* in_sizes, int n_in,
                              void* d_out, int out_size)
{
    const float* X = (const float*)d_in[0];
    const float* Y = (const float*)d_in[1];
    float* out = (float*)d_out;

    static bool attr_done = false;
    if (!attr_done) {
        cudaFuncSetAttribute(gemm_kernel,
                             cudaFuncAttributeMaxDynamicSharedMemorySize,
                             SMEM_BYTES);
        attr_done = true;
    }

    dz_kernel<<<384, 256>>>(X, Y);
    gemm_kernel<<<NTRI, 256, SMEM_BYTES>>>();
    pde_kernel<<<PDE_CTAS, 256>>>(X, Y, out);
}